// round 16
// baseline (speedup 1.0000x reference)
#include <cuda_runtime.h>
#include <math.h>
#include <float.h>

#define NB 1024
#define LL 200
#define DD 128
#define KK 3
#define NEG_PAD (-65535.0f)

// Shared layout (floats), total 28576 = 114304 B -> 2 CTAs/SM:
//  cap_t [0,25728)       quad-transposed tile: quad q of row l at
//                        float offset 4*(q*201 + l). 16B-aligned for all l;
//                        staging STS.128 and delta LDS.128 both conflict-free.
//  W4    [25728,26528)   [200][4] softmax weights; first 512 reused as h4
//  SCR   [26528,28064)   [4][384] reduction slots; first 384 reused as gk[3][128]
//  u4p   [28064,28576)   [128][4] u packed for float4 broadcast
#define OFF_W4   25728
#define OFF_SCR  26528
#define OFF_U4P  28064
#define SM_FLOATS 28576
#define SMEM_BYTES (SM_FLOATS * 4)

__device__ float g_B[KK * LL];
__device__ float g_delta[3][KK * LL];
__device__ float g_ST[DD * DD];         // ST[e*128+d] = S[d*128+e]

__global__ void routing_init_kernel(const float* __restrict__ Bin,
                                    const float* __restrict__ S)
{
    int idx = blockIdx.x * 256 + threadIdx.x;
    int d = idx >> 7;
    int e = idx & 127;
    g_ST[e * DD + d] = S[idx];
    if (blockIdx.x == 0) {
        for (int t = threadIdx.x; t < KK * LL; t += 256) {
            g_B[t] = Bin[t];
            g_delta[0][t] = 0.f;
            g_delta[1][t] = 0.f;
            g_delta[2][t] = 0.f;
        }
    }
}

__global__ void routing_update_kernel(int it)
{
    int t = threadIdx.x;
    if (t < KK * LL) g_B[t] += g_delta[it][t];
}

__global__ void __launch_bounds__(384, 2)
routing_iter_kernel(const float* __restrict__ cap,
                    const float* __restrict__ S,
                    const void*  __restrict__ seqp,
                    int it,
                    float* __restrict__ out)
{
    extern __shared__ float sm[];
    float* cap_t = sm;
    float* W4    = sm + OFF_W4;
    float* h4    = sm + OFF_W4;        // overlays W4 (dead after sweep)
    float* scr   = sm + OFF_SCR;
    float* gk    = sm + OFF_SCR;       // gk[k][128], overlays scratch after g fold
    float* u4p   = sm + OFF_U4P;

    const int b    = blockIdx.x;
    const int tid  = threadIdx.x;
    const int warp = tid >> 5;
    const int lane = tid & 31;

    // ---- sequence length (int32 vs int64 robust) --------------------------
    int n;
    {
        const int* si = (const int*)seqp;
        if (si[1] == 0) n = (int)(((const long long*)seqp)[b]);
        else            n = si[b];
    }

    // ---- masked softmax over L for the 3 routing rows (warps 0-2) ---------
    if (warp < 3) {
        const int k = warp;
        float v[7];
        float mx = -FLT_MAX;
        #pragma unroll
        for (int i = 0; i < 7; i++) {
            int l = lane + 32 * i;
            float x = -FLT_MAX;
            if (l < LL) x = (l < n) ? g_B[k * LL + l] : NEG_PAD;
            v[i] = x;
            mx = fmaxf(mx, x);
        }
        #pragma unroll
        for (int off = 16; off; off >>= 1)
            mx = fmaxf(mx, __shfl_xor_sync(0xffffffffu, mx, off));
        float s = 0.f;
        #pragma unroll
        for (int i = 0; i < 7; i++) {
            int l = lane + 32 * i;
            float e = (l < LL) ? expf(v[i] - mx) : 0.f;
            v[i] = e;
            s += e;
        }
        #pragma unroll
        for (int off = 16; off; off >>= 1)
            s += __shfl_xor_sync(0xffffffffu, s, off);
        float inv = 1.f / s;
        #pragma unroll
        for (int i = 0; i < 7; i++) {
            int l = lane + 32 * i;
            if (l < LL) {
                W4[l * 4 + k] = v[i] * inv;
                W4[l * 4 + 3] = 0.f;       // .w lane of the broadcast
            }
        }
    }
    __syncthreads();

    // ---- fused sweep: stage cap (quad-transposed) AND accumulate u --------
    // 12 warps own contiguous row blocks: warps 0-7 -> 17 rows, 8-11 -> 16.
    // Lanes own d-quads (q=lane); warp-row load is one coalesced LDG.128/lane.
    const float4* capb = (const float4*)(cap + (size_t)b * (LL * DD));
    float4 a0 = make_float4(0.f, 0.f, 0.f, 0.f);
    float4 a1 = a0, a2 = a0;
    {
        const int rbase = (warp < 8) ? warp * 17 : 136 + (warp - 8) * 16;
        #pragma unroll
        for (int bb = 0; bb < 4; bb++) {           // itx 0..15 (all warps)
            float4 c[4];
            #pragma unroll
            for (int u = 0; u < 4; u++)            // batched LDG.128: MLP=4
                c[u] = capb[(rbase + bb * 4 + u) * 32 + lane];
            #pragma unroll
            for (int u = 0; u < 4; u++) {
                int l = rbase + bb * 4 + u;        // uniform per warp
                float4 wv = *(const float4*)(W4 + l * 4);   // 1 bcast / row
                a0.x = fmaf(wv.x, c[u].x, a0.x); a0.y = fmaf(wv.x, c[u].y, a0.y);
                a0.z = fmaf(wv.x, c[u].z, a0.z); a0.w = fmaf(wv.x, c[u].w, a0.w);
                a1.x = fmaf(wv.y, c[u].x, a1.x); a1.y = fmaf(wv.y, c[u].y, a1.y);
                a1.z = fmaf(wv.y, c[u].z, a1.z); a1.w = fmaf(wv.y, c[u].w, a1.w);
                a2.x = fmaf(wv.z, c[u].x, a2.x); a2.y = fmaf(wv.z, c[u].y, a2.y);
                a2.z = fmaf(wv.z, c[u].z, a2.z); a2.w = fmaf(wv.z, c[u].w, a2.w);
                *(float4*)(cap_t + 4 * (lane * 201 + l)) = c[u];  // STS.128 cf
            }
        }
        if (warp < 8) {                            // itx 16: 17th row
            int l = rbase + 16;
            float4 c = capb[l * 32 + lane];
            float4 wv = *(const float4*)(W4 + l * 4);
            a0.x = fmaf(wv.x, c.x, a0.x); a0.y = fmaf(wv.x, c.y, a0.y);
            a0.z = fmaf(wv.x, c.z, a0.z); a0.w = fmaf(wv.x, c.w, a0.w);
            a1.x = fmaf(wv.y, c.x, a1.x); a1.y = fmaf(wv.y, c.y, a1.y);
            a1.z = fmaf(wv.y, c.z, a1.z); a1.w = fmaf(wv.y, c.w, a1.w);
            a2.x = fmaf(wv.z, c.x, a2.x); a2.y = fmaf(wv.z, c.y, a2.y);
            a2.z = fmaf(wv.z, c.z, a2.z); a2.w = fmaf(wv.z, c.w, a2.w);
            *(float4*)(cap_t + 4 * (lane * 201 + l)) = c;
        }
    }
    // 12 partials -> 4 slots in 3 exclusive phases (no atomics, no selects)
    if (warp < 4) {
        float* rp = scr + warp * 384 + 4 * lane;
        *(float4*)(rp)       = a0;
        *(float4*)(rp + 128) = a1;
        *(float4*)(rp + 256) = a2;
    }
    __syncthreads();
    if (warp >= 4 && warp < 8) {
        float* rp = scr + (warp - 4) * 384 + 4 * lane;
        float4 t0 = *(float4*)(rp);
        float4 t1 = *(float4*)(rp + 128);
        float4 t2 = *(float4*)(rp + 256);
        t0.x += a0.x; t0.y += a0.y; t0.z += a0.z; t0.w += a0.w;
        t1.x += a1.x; t1.y += a1.y; t1.z += a1.z; t1.w += a1.w;
        t2.x += a2.x; t2.y += a2.y; t2.z += a2.z; t2.w += a2.w;
        *(float4*)(rp)       = t0;
        *(float4*)(rp + 128) = t1;
        *(float4*)(rp + 256) = t2;
    }
    __syncthreads();
    if (warp >= 8) {
        float* rp = scr + (warp - 8) * 384 + 4 * lane;
        float4 t0 = *(float4*)(rp);
        float4 t1 = *(float4*)(rp + 128);
        float4 t2 = *(float4*)(rp + 256);
        t0.x += a0.x; t0.y += a0.y; t0.z += a0.z; t0.w += a0.w;
        t1.x += a1.x; t1.y += a1.y; t1.z += a1.z; t1.w += a1.w;
        t2.x += a2.x; t2.y += a2.y; t2.z += a2.z; t2.w += a2.w;
        *(float4*)(rp)       = t0;
        *(float4*)(rp + 128) = t1;
        *(float4*)(rp + 256) = t2;
    }
    __syncthreads();
    if (tid < 128) {                       // fold 4 slots -> u4p [d][4]
        float s0 = 0.f, s1 = 0.f, s2 = 0.f;
        #pragma unroll
        for (int s = 0; s < 4; s++) {
            s0 += scr[s * 384 +       tid];
            s1 += scr[s * 384 + 128 + tid];
            s2 += scr[s * 384 + 256 + tid];
        }
        *(float4*)(u4p + tid * 4) = make_float4(s0, s1, s2, 0.f);
    }
    __syncthreads();

    // ---- hraw[k,e] = sum_d u[k,d]*S[d,e] : warps 0-7 own 16-d strips ------
    {
        float4 b0 = make_float4(0.f, 0.f, 0.f, 0.f);
        float4 b1 = b0, b2 = b0;
        if (warp < 8) {
            const int d0 = warp * 16;
            #pragma unroll
            for (int dd = 0; dd < 16; dd++) {
                int d = d0 + dd;
                float4 sv = *(const float4*)(S + d * DD + 4 * lane);  // LDG.128
                float4 uv = *(const float4*)(u4p + d * 4);            // broadcast
                b0.x = fmaf(uv.x, sv.x, b0.x); b0.y = fmaf(uv.x, sv.y, b0.y);
                b0.z = fmaf(uv.x, sv.z, b0.z); b0.w = fmaf(uv.x, sv.w, b0.w);
                b1.x = fmaf(uv.y, sv.x, b1.x); b1.y = fmaf(uv.y, sv.y, b1.y);
                b1.z = fmaf(uv.y, sv.z, b1.z); b1.w = fmaf(uv.y, sv.w, b1.w);
                b2.x = fmaf(uv.z, sv.x, b2.x); b2.y = fmaf(uv.z, sv.y, b2.y);
                b2.z = fmaf(uv.z, sv.z, b2.z); b2.w = fmaf(uv.z, sv.w, b2.w);
            }
        }
        if (warp < 4) {
            float* rp = scr + warp * 384 + 4 * lane;
            *(float4*)(rp)       = b0;
            *(float4*)(rp + 128) = b1;
            *(float4*)(rp + 256) = b2;
        }
        __syncthreads();
        if (warp >= 4 && warp < 8) {
            float* rp = scr + (warp - 4) * 384 + 4 * lane;
            float4 t0 = *(float4*)(rp);
            float4 t1 = *(float4*)(rp + 128);
            float4 t2 = *(float4*)(rp + 256);
            t0.x += b0.x; t0.y += b0.y; t0.z += b0.z; t0.w += b0.w;
            t1.x += b1.x; t1.y += b1.y; t1.z += b1.z; t1.w += b1.w;
            t2.x += b2.x; t2.y += b2.y; t2.z += b2.z; t2.w += b2.w;
            *(float4*)(rp)       = t0;
            *(float4*)(rp + 128) = t1;
            *(float4*)(rp + 256) = t2;
        }
        __syncthreads();
        if (tid < 128) {                   // fold -> h4 (overlays dead W4)
            float s0 = 0.f, s1 = 0.f, s2 = 0.f;
            #pragma unroll
            for (int s = 0; s < 4; s++) {
                s0 += scr[s * 384 +       tid];
                s1 += scr[s * 384 + 128 + tid];
                s2 += scr[s * 384 + 256 + tid];
            }
            *(float4*)(h4 + tid * 4) = make_float4(s0, s1, s2, 0.f);
        }
    }
    __syncthreads();

    // ---- squash over k, write output, rescale h4 in place -----------------
    if (tid < 128) {
        const int e = tid;
        float4 hv = *(const float4*)(h4 + e * 4);
        float sq = hv.x * hv.x + hv.y * hv.y + hv.z * hv.z;
        float scale = (sq / (1.f + sq)) * rsqrtf(sq + 1e-9f);
        hv.x *= scale; hv.y *= scale; hv.z *= scale;
        float* op = out + (size_t)b * (KK * DD) + e;
        op[0]      = hv.x;
        op[DD]     = hv.y;
        op[2 * DD] = hv.z;
        *(float4*)(h4 + e * 4) = make_float4(hv.x, hv.y, hv.z, 0.f);
    }
    __syncthreads();

    // ---- g[k,d] = sum_e high[k,e]*ST[e,d] : warps 0-7 own 16-e strips -----
    {
        float4 b0 = make_float4(0.f, 0.f, 0.f, 0.f);
        float4 b1 = b0, b2 = b0;
        if (warp < 8) {
            const int e0 = warp * 16;
            #pragma unroll
            for (int ee = 0; ee < 16; ee++) {
                int e = e0 + ee;
                float4 sv = *(const float4*)(g_ST + e * DD + 4 * lane); // LDG.128
                float4 hv = *(const float4*)(h4 + e * 4);               // broadcast
                b0.x = fmaf(hv.x, sv.x, b0.x); b0.y = fmaf(hv.x, sv.y, b0.y);
                b0.z = fmaf(hv.x, sv.z, b0.z); b0.w = fmaf(hv.x, sv.w, b0.w);
                b1.x = fmaf(hv.y, sv.x, b1.x); b1.y = fmaf(hv.y, sv.y, b1.y);
                b1.z = fmaf(hv.y, sv.z, b1.z); b1.w = fmaf(hv.y, sv.w, b1.w);
                b2.x = fmaf(hv.z, sv.x, b2.x); b2.y = fmaf(hv.z, sv.y, b2.y);
                b2.z = fmaf(hv.z, sv.z, b2.z); b2.w = fmaf(hv.z, sv.w, b2.w);
            }
        }
        if (warp < 4) {
            float* rp = scr + warp * 384 + 4 * lane;
            *(float4*)(rp)       = b0;
            *(float4*)(rp + 128) = b1;
            *(float4*)(rp + 256) = b2;
        }
        __syncthreads();
        if (warp >= 4 && warp < 8) {
            float* rp = scr + (warp - 4) * 384 + 4 * lane;
            float4 t0 = *(float4*)(rp);
            float4 t1 = *(float4*)(rp + 128);
            float4 t2 = *(float4*)(rp + 256);
            t0.x += b0.x; t0.y += b0.y; t0.z += b0.z; t0.w += b0.w;
            t1.x += b1.x; t1.y += b1.y; t1.z += b1.z; t1.w += b1.w;
            t2.x += b2.x; t2.y += b2.y; t2.z += b2.z; t2.w += b2.w;
            *(float4*)(rp)       = t0;
            *(float4*)(rp + 128) = t1;
            *(float4*)(rp + 256) = t2;
        }
        __syncthreads();
        // fold into registers, barrier, THEN write gk[3][128] over scratch
        float s0 = 0.f, s1 = 0.f, s2 = 0.f;
        if (tid < 128) {
            #pragma unroll
            for (int s = 0; s < 4; s++) {
                s0 += scr[s * 384 +       tid];
                s1 += scr[s * 384 + 128 + tid];
                s2 += scr[s * 384 + 256 + tid];
            }
        }
        __syncthreads();                   // all reads done before overwrite
        if (tid < 128) {
            gk[tid]       = s0;            // gk[0][d]
            gk[128 + tid] = s1;            // gk[1][d]
            gk[256 + tid] = s2;            // gk[2][d]
        }
    }
    __syncthreads();

    // ---- delta[k,l] += sum_d g[k,d]*cap[l,d] : thread-per-row, quad loads -
    if (tid < LL) {
        const int l = tid;
        float d0 = 0.f, d1 = 0.f, d2 = 0.f;
        #pragma unroll
        for (int jb = 0; jb < 8; jb++) {           // 8 batches x 4 quads
            float4 c[4];
            #pragma unroll
            for (int u = 0; u < 4; u++)            // batched LDS.128: MLP=4
                c[u] = *(const float4*)(cap_t + 4 * ((jb * 4 + u) * 201 + l));
            #pragma unroll
            for (int u = 0; u < 4; u++) {
                int j = jb * 4 + u;
                float4 q0 = *(const float4*)(gk +       4 * j);  // broadcast
                float4 q1 = *(const float4*)(gk + 128 + 4 * j);  // broadcast
                float4 q2 = *(const float4*)(gk + 256 + 4 * j);  // broadcast
                d0 = fmaf(q0.x, c[u].x, fmaf(q0.y, c[u].y,
                     fmaf(q0.z, c[u].z, fmaf(q0.w, c[u].w, d0))));
                d1 = fmaf(q1.x, c[u].x, fmaf(q1.y, c[u].y,
                     fmaf(q1.z, c[u].z, fmaf(q1.w, c[u].w, d1))));
                d2 = fmaf(q2.x, c[u].x, fmaf(q2.y, c[u].y,
                     fmaf(q2.z, c[u].z, fmaf(q2.w, c[u].w, d2))));
            }
        }
        float* dp = g_delta[it];
        atomicAdd(dp + l,          d0);
        atomicAdd(dp + LL + l,     d1);
        atomicAdd(dp + 2 * LL + l, d2);
    }
}

extern "C" void kernel_launch(void* const* d_in, const int* in_sizes, int n_in,
                              void* d_out, int out_size)
{
    (void)in_sizes; (void)n_in; (void)out_size;
    const float* cap  = (const float*)d_in[0];
    const float* Bin  = (const float*)d_in[1];
    const float* S    = (const float*)d_in[2];
    const void*  seqp = d_in[3];
    float* out = (float*)d_out;

    cudaFuncSetAttribute(routing_iter_kernel,
                         cudaFuncAttributeMaxDynamicSharedMemorySize, SMEM_BYTES);

    routing_init_kernel<<<64, 256>>>(Bin, S);

    routing_iter_kernel<<<NB, 384, SMEM_BYTES>>>(cap, S, seqp, 0, out);
    routing_update_kernel<<<1, 600>>>(0);
    routing_iter_kernel<<<NB, 384, SMEM_BYTES>>>(cap, S, seqp, 1, out);
    routing_update_kernel<<<1, 600>>>(1);
    routing_iter_kernel<<<NB, 384, SMEM_BYTES>>>(cap, S, seqp, 2, out);
}